// round 1
// baseline (speedup 1.0000x reference)
#include <cuda_runtime.h>

// ResidualEmbedding: per-frame Burg LPC (order 12) residual, sign-modulated embed.
// Layout: one warp per frame (160 samples, 5 per lane, stride-32).
// F/B error arrays kept in registers, mirrored in warp-private shared memory for
// the cross-offset reads (offset = i+1 grows per iteration). Only __syncwarp.

namespace {

constexpr int FRAME   = 160;
constexpr int KFR     = 15;
constexpr int ORDER   = 12;
constexpr int BATCH   = 4096;
constexpr int NFRAMES = BATCH * KFR;     // 61440
constexpr int WPB     = 8;               // warps (frames) per block
constexpr int THREADS = WPB * 32;
constexpr unsigned FULL = 0xffffffffu;

__device__ __forceinline__ float warp_sum(float v) {
#pragma unroll
    for (int o = 16; o > 0; o >>= 1) v += __shfl_xor_sync(FULL, v, o);
    return v;
}

__global__ __launch_bounds__(THREADS) void burg_residual_kernel(
    const int*   __restrict__ bits,
    const float* __restrict__ pcm,
    const float* __restrict__ alpha_p,
    float*       __restrict__ out)
{
    const int warp  = threadIdx.x >> 5;
    const int lane  = threadIdx.x & 31;
    const int frame = blockIdx.x * WPB + warp;
    if (frame >= NFRAMES) return;

    __shared__ float shX[WPB][FRAME];
    __shared__ float shF[WPB][FRAME];
    __shared__ float shB[WPB][FRAME];
    float* __restrict__ X  = shX[warp];
    float* __restrict__ Fh = shF[warp];
    float* __restrict__ Bh = shB[warp];

    const float* __restrict__ src = pcm + (long long)frame * FRAME;

    // ---- Load frame, window (np.hanning: 0.5 - 0.5*cos(2*pi*n/159)), init F/B, den ----
    float x[5], Freg[5], Breg[5];
    float part = 0.f;
#pragma unroll
    for (int q = 0; q < 5; ++q) {
        const int m = lane + 32 * q;
        const float v = src[m];
        x[q] = v;
        const float w  = 0.5f - 0.5f * cosf((6.283185307179586f / 159.0f) * (float)m);
        const float xw = v * w;
        Freg[q] = xw;               // f[j] = xw[j+1]  -> sample-space F[m], valid m in [1,159]
        Breg[q] = xw;               // b[j] = xw[j]    -> sample-space B[m], valid m in [0,158]
        X[m]  = v;
        Fh[m] = xw;
        Bh[m] = xw;
        // den = sum(f^2) + sum(b^2): weight 2 everywhere except the ends.
        const float c = (m == 0 || m == 159) ? 1.f : 2.f;
        part += c * xw * xw;
    }
    float den = warp_sum(part);
    __syncwarp();

    float a[ORDER + 1];
    a[0] = 1.f;
#pragma unroll
    for (int k = 1; k <= ORDER; ++k) a[k] = 0.f;

    // ---- Burg recursion, fully unrolled (compile-time i => no reg-array spills) ----
    // At iteration i: f_i valid over samples [i+1,159], b_i over [0,158-i].
    // f_i[j] = F[j+i+1], b_i[j] = B[j], j in [0,158-i].
#pragma unroll
    for (int i = 0; i < ORDER; ++i) {
        // reduction: sum_j b_i[j] * f_i[j]  (lane owns b at m = lane+32q)
        float fc[5];
        float p = 0.f;
#pragma unroll
        for (int q = 0; q < 5; ++q) {
            const int m = lane + 32 * q;
            const bool v = (m <= 158 - i);
            fc[q] = v ? Fh[m + i + 1] : 0.f;        // f_i[j=m]
            p    += v ? fc[q] * Breg[q] : 0.f;
        }
        const float s = warp_sum(p);
        const float r = -2.f * s / den;

        // cross loads for the f-update: B[m-i-1] (old values; stores happen after syncwarp)
        float bc[5];
#pragma unroll
        for (int q = 0; q < 5; ++q) {
            const int m = lane + 32 * q;
            bc[q] = (m >= i + 1) ? Bh[m - i - 1] : 0.f;
        }
        __syncwarp();   // all old-value reads complete before anyone stores

        // in-place (sample-space) update:
        //   F[m] += r * B[m-i-1]  for m in [i+1,159]   (f_new, pre-trim)
        //   B[m] += r * F[m+i+1]  for m in [0,158-i]   (b_new, pre-trim; uses old F = fc)
#pragma unroll
        for (int q = 0; q < 5; ++q) {
            const int m = lane + 32 * q;
            if (m >= i + 1)    { Freg[q] += r * bc[q]; Fh[m] = Freg[q]; }
            if (m <= 158 - i)  { Breg[q] += r * fc[q]; Bh[m] = Breg[q]; }
        }
        __syncwarp();

        // den_{i+1} = (1-r^2)*den - b_new[last]^2 - f_new[0]^2
        // f_new[0] at sample m=i+1 (q=0, lane=i+1); b_new[last] at m=158-i (q=4, lane=30-i)
        const float f0 = __shfl_sync(FULL, Freg[0], i + 1);
        const float bl = __shfl_sync(FULL, Breg[4], 30 - i);
        den = (1.f - r * r) * den - bl * bl - f0 * f0;

        // a[:i+2] += r * reverse(a[:i+2])  (simultaneous; all indices compile-time)
        float an[ORDER + 1];
#pragma unroll
        for (int k = 0; k <= ORDER; ++k)
            an[k] = (k <= i + 1) ? (a[k] + r * a[i + 1 - k]) : a[k];
#pragma unroll
        for (int k = 0; k <= ORDER; ++k) a[k] = an[k];
    }

    // ---- FIR on the RAW (unwindowed) frame + output ----
    const float sgn  = 2.f * (float)__ldg(&bits[frame]) - 1.f;
    const float coef = __ldg(alpha_p) * sgn;
    float* __restrict__ dst = out + (long long)frame * FRAME;

#pragma unroll
    for (int q = 0; q < 5; ++q) {
        const int m = lane + 32 * q;
        float acc = a[0] * x[q];
#pragma unroll
        for (int k = 1; k <= ORDER; ++k) {
            acc += (m - k >= 0) ? a[k] * X[m - k] : 0.f;
        }
        dst[m] = x[q] + coef * acc;
    }
}

} // namespace

extern "C" void kernel_launch(void* const* d_in, const int* in_sizes, int n_in,
                              void* d_out, int out_size)
{
    const int*   bits  = (const int*)  d_in[0];
    const float* pcm   = (const float*)d_in[1];
    const float* alpha = (const float*)d_in[2];
    float*       out   = (float*)d_out;

    const int grid = (NFRAMES + WPB - 1) / WPB;   // 7680 blocks
    burg_residual_kernel<<<grid, THREADS>>>(bits, pcm, alpha, out);
}

// round 2
// speedup vs baseline: 1.1950x; 1.1950x over previous
#include <cuda_runtime.h>

// ResidualEmbedding: per-frame Burg LPC (order 12) residual, sign-modulated embed.
// R2: F/B error arrays fully register-resident; all cross-offset accesses
// (distance d=i+1<=12 < 32) done with warp shuffles instead of shared memory.
// Shared memory holds only the raw frame X for the FIR taps.

namespace {

constexpr int FRAME   = 160;
constexpr int KFR     = 15;
constexpr int ORDER   = 12;
constexpr int BATCH   = 4096;
constexpr int NFRAMES = BATCH * KFR;     // 61440
constexpr int WPB     = 8;               // warps (frames) per block
constexpr int THREADS = WPB * 32;
constexpr unsigned FULL = 0xffffffffu;

__device__ __forceinline__ float warp_sum(float v) {
#pragma unroll
    for (int o = 16; o > 0; o >>= 1) v += __shfl_xor_sync(FULL, v, o);
    return v;
}

__global__ __launch_bounds__(THREADS) void burg_residual_kernel(
    const int*   __restrict__ bits,
    const float* __restrict__ pcm,
    const float* __restrict__ alpha_p,
    float*       __restrict__ out)
{
    const int warp  = threadIdx.x >> 5;
    const int lane  = threadIdx.x & 31;
    const int frame = blockIdx.x * WPB + warp;
    if (frame >= NFRAMES) return;

    __shared__ float shX[WPB][FRAME];
    float* __restrict__ X = shX[warp];

    const float* __restrict__ src = pcm + (long long)frame * FRAME;

    // ---- Load frame, window (np.hanning: 0.5 - 0.5*cos(2*pi*m/159)), init F/B, den ----
    // Sample-space: F[m] (valid m in [i+1,159]), B[m] (valid m in [0,158-i]).
    // Lane owns samples m = lane + 32q, q=0..4 (stride-32).
    float x[5], F[5], Bv[5];
    float part = 0.f;
#pragma unroll
    for (int q = 0; q < 5; ++q) {
        const int m = lane + 32 * q;
        const float v = src[m];
        x[q] = v;
        X[m] = v;
        const float w  = 0.5f - 0.5f * cosf((6.283185307179586f / 159.0f) * (float)m);
        const float xw = v * w;
        F[q]  = xw;
        Bv[q] = xw;
        const float c = (m == 0 || m == 159) ? 1.f : 2.f;   // den double-counts interior
        part += c * xw * xw;
    }
    float den = warp_sum(part);

    float a[ORDER + 1];
    a[0] = 1.f;
#pragma unroll
    for (int k = 1; k <= ORDER; ++k) a[k] = 0.f;

    // ---- Burg recursion, fully unrolled; cross access via shuffles ----
#pragma unroll
    for (int i = 0; i < ORDER; ++i) {
        const int d = i + 1;

        // fc[q] = F[m+d]  (masked 0 beyond m = 158-i; only the q=4 chunk can violate)
        float sF[5];
#pragma unroll
        for (int q = 0; q < 5; ++q)
            sF[q] = __shfl_sync(FULL, F[q], (lane + d) & 31);
        float fc[5];
#pragma unroll
        for (int q = 0; q < 4; ++q)
            fc[q] = (lane + d < 32) ? sF[q] : sF[q + 1];
        fc[4] = (lane <= 30 - i) ? sF[4] : 0.f;   // m=128+lane <= 158-i  <=> lane+d<32

        // dot: sum_m F[m+d] * B[m]   (fc already 0 where invalid)
        float p = 0.f;
#pragma unroll
        for (int q = 0; q < 5; ++q) p += fc[q] * Bv[q];
        const float s = warp_sum(p);
        const float r = -2.f * s / den;

        // bc[q] = B[m-d]  (masked 0 below m = d; only the q=0 chunk can violate)
        float sB[5];
#pragma unroll
        for (int q = 0; q < 5; ++q)
            sB[q] = __shfl_sync(FULL, Bv[q], (lane - d) & 31);
        float bc[5];
        bc[0] = (lane >= d) ? sB[0] : 0.f;
#pragma unroll
        for (int q = 1; q < 5; ++q)
            bc[q] = (lane >= d) ? sB[q] : sB[q - 1];

        // updates (stale out-of-range entries get +0 or are never read again)
#pragma unroll
        for (int q = 0; q < 5; ++q) {
            F[q]  += r * bc[q];   // F[m] += r*B[m-d]
            Bv[q] += r * fc[q];   // B[m] += r*F[m+d]
        }

        // den_{i+1} = (1-r^2)*den - b_new[last]^2 - f_new[0]^2
        const float f0 = __shfl_sync(FULL, F[0],  d);        // F[d]      (q=0, lane=d)
        const float bl = __shfl_sync(FULL, Bv[4], 30 - i);   // B[158-i]  (q=4, lane=30-i)
        den = (1.f - r * r) * den - bl * bl - f0 * f0;

        // a[:i+2] += r * reverse(a[:i+2])  (simultaneous, compile-time indices)
        float an[ORDER + 1];
#pragma unroll
        for (int k = 0; k <= ORDER; ++k)
            an[k] = (k <= i + 1) ? (a[k] + r * a[i + 1 - k]) : a[k];
#pragma unroll
        for (int k = 0; k <= ORDER; ++k) a[k] = an[k];
    }

    // ---- FIR on the RAW (unwindowed) frame + embed ----
    __syncwarp();   // X stores (top) visible before cross-lane FIR reads
    const float sgn  = 2.f * (float)__ldg(&bits[frame]) - 1.f;
    const float coef = __ldg(alpha_p) * sgn;
    float* __restrict__ dst = out + (long long)frame * FRAME;

#pragma unroll
    for (int q = 0; q < 5; ++q) {
        const int m = lane + 32 * q;
        float acc = a[0] * x[q];
#pragma unroll
        for (int k = 1; k <= ORDER; ++k) {
            acc += (m - k >= 0) ? a[k] * X[m - k] : 0.f;
        }
        dst[m] = x[q] + coef * acc;
    }
}

} // namespace

extern "C" void kernel_launch(void* const* d_in, const int* in_sizes, int n_in,
                              void* d_out, int out_size)
{
    const int*   bits  = (const int*)  d_in[0];
    const float* pcm   = (const float*)d_in[1];
    const float* alpha = (const float*)d_in[2];
    float*       out   = (float*)d_out;

    const int grid = (NFRAMES + WPB - 1) / WPB;   // 7680 blocks
    burg_residual_kernel<<<grid, THREADS>>>(bits, pcm, alpha, out);
}

// round 4
// speedup vs baseline: 1.7623x; 1.4748x over previous
#include <cuda_runtime.h>

// ResidualEmbedding: per-frame Burg LPC (order 12) residual, sign-modulated embed.
// R4: contiguous lane ownership (lane L owns j in [5L,5L+4]).
//  - Burg in j-space: t=f+r*b, u=b+r*f, f'=shift1(t), b'=u.
//    shift-by-1 = 4 reg moves + 1 SHFL. Zero-propagation invariant on the
//    invalid tail removes all dot/den masking (2 cheap zeroings per iter).
//  - Reductions: 5-step butterfly (redux.f32 doesn't exist on sm_103).
//  - FIR fully register-resident: 17-float window per lane from shared (stride-5,
//    conflict-free), 65 FMAs, no per-tap LDS.
//  - Coalesced global I/O via shared-memory transposes (buffer reused).

namespace {

constexpr int FRAME   = 160;
constexpr int KFR     = 15;
constexpr int ORDER   = 12;
constexpr int BATCH   = 4096;
constexpr int NFRAMES = BATCH * KFR;     // 61440
constexpr int WPB     = 8;               // warps (frames) per block
constexpr int THREADS = WPB * 32;
constexpr unsigned FULL = 0xffffffffu;

__device__ __forceinline__ float warp_sum(float v) {
#pragma unroll
    for (int o = 16; o > 0; o >>= 1) v += __shfl_xor_sync(FULL, v, o);
    return v;
}

__global__ __launch_bounds__(THREADS) void burg_residual_kernel(
    const int*   __restrict__ bits,
    const float* __restrict__ pcm,
    const float* __restrict__ alpha_p,
    float*       __restrict__ out)
{
    const int warp  = threadIdx.x >> 5;
    const int lane  = threadIdx.x & 31;
    const int frame = blockIdx.x * WPB + warp;
    if (frame >= NFRAMES) return;

    __shared__ float shX[WPB][FRAME];
    float* __restrict__ X = shX[warp];

    const float* __restrict__ src = pcm + (long long)frame * FRAME;

    // ---- Coalesced load into shared (raw samples) ----
#pragma unroll
    for (int q = 0; q < 5; ++q) {
        const int m = lane + 32 * q;
        X[m] = src[m];
    }
    __syncwarp();

    // ---- Windowed samples for my contiguous chunk j = 5*lane + c ----
    const int base = 5 * lane;
    float xw[5];
#pragma unroll
    for (int c = 0; c < 5; ++c) {
        const int j = base + c;
        const float w = 0.5f - 0.5f * __cosf((6.283185307179586f / 159.0f) * (float)j);
        xw[c] = X[j] * w;
    }

    // ---- Init: b[j]=xw[j] (j<=158), f[j]=xw[j+1] (j<=158); j=159 entries = 0 ----
    float f[5], b[5];
#pragma unroll
    for (int c = 0; c < 5; ++c) b[c] = xw[c];
#pragma unroll
    for (int c = 0; c < 4; ++c) f[c] = xw[c + 1];
    {
        const float nxt = __shfl_sync(FULL, xw[0], (lane + 1) & 31);
        f[4] = nxt;
    }
    if (lane == 31) { f[4] = 0.f; b[4] = 0.f; }   // j=159 invalid -> keep 0

    // den = sum f^2 + b^2 (invalid entries are 0, no mask needed)
    float p0 = 0.f;
#pragma unroll
    for (int c = 0; c < 5; ++c) p0 += f[c] * f[c] + b[c] * b[c];
    float den = warp_sum(p0);

    float a[ORDER + 1];
    a[0] = 1.f;
#pragma unroll
    for (int k = 1; k <= ORDER; ++k) a[k] = 0.f;

    // ---- Burg recursion. Invariant at iter i entry: f[j]=b[j]=0 for j >= 159-i ----
#pragma unroll
    for (int i = 0; i < ORDER; ++i) {
        // dot = sum_j f[j]*b[j]  (tails are zero -> unmasked)
        float p = 0.f;
#pragma unroll
        for (int c = 0; c < 5; ++c) p += f[c] * b[c];
        const float s = warp_sum(p);
        const float r = -2.f * s / den;

        float t[5], u[5];
#pragma unroll
        for (int c = 0; c < 5; ++c) {
            t[c] = fmaf(r, b[c], f[c]);   // new f (pre-trim)
            u[c] = fmaf(r, f[c], b[c]);   // new b (pre-trim)
        }

        // den update needs new f[0] and new b[158-i]
        const int jl = 158 - i;            // compile-time (unrolled)
        const int Ll = jl / 5, cl = jl % 5;
        const float t0 = __shfl_sync(FULL, t[0], 0);
        const float ul = __shfl_sync(FULL, u[cl], Ll);
        den = (1.f - r * r) * den - ul * ul - t0 * t0;

        // f' = shift-by-1 of t (zero the lane-31 wrap); b' = u with last valid zeroed
        const float tn = __shfl_sync(FULL, t[0], (lane + 1) & 31);
#pragma unroll
        for (int c = 0; c < 4; ++c) f[c] = t[c + 1];
        f[4] = (lane == 31) ? 0.f : tn;
#pragma unroll
        for (int c = 0; c < 5; ++c) b[c] = u[c];
        if (lane == Ll) b[cl] = 0.f;       // j=158-i becomes invalid

        // a[:i+2] += r * reverse(a[:i+2])  -- pairwise in place
#pragma unroll
        for (int k = 0; 2 * k <= i + 1; ++k) {
            const int k2 = i + 1 - k;
            if (k2 == k) {
                a[k] = a[k] + r * a[k];
            } else {
                const float tmp = a[k];
                a[k]  = fmaf(r, a[k2], a[k]);
                a[k2] = fmaf(r, tmp,  a[k2]);
            }
        }
    }

    // ---- FIR on raw samples, fully register-resident ----
    float xf[17];   // X[base-12 .. base+4]
#pragma unroll
    for (int t = 0; t < 17; ++t) {
        const int idx = base - 12 + t;
        xf[t] = (idx >= 0) ? X[idx] : 0.f;
    }

    const float sgn  = 2.f * (float)__ldg(&bits[frame]) - 1.f;
    const float coef = __ldg(alpha_p) * sgn;

    float o[5];
#pragma unroll
    for (int c = 0; c < 5; ++c) {
        float acc = a[0] * xf[12 + c];
#pragma unroll
        for (int k = 1; k <= ORDER; ++k)
            acc = fmaf(a[k], xf[12 + c - k], acc);
        o[c] = fmaf(coef, acc, xf[12 + c]);
    }

    // ---- Transpose through shared for coalesced store ----
    __syncwarp();                 // all xf reads done before overwrite
#pragma unroll
    for (int c = 0; c < 5; ++c) X[base + c] = o[c];
    __syncwarp();

    float* __restrict__ dst = out + (long long)frame * FRAME;
#pragma unroll
    for (int q = 0; q < 5; ++q) {
        const int m = lane + 32 * q;
        dst[m] = X[m];
    }
}

} // namespace

extern "C" void kernel_launch(void* const* d_in, const int* in_sizes, int n_in,
                              void* d_out, int out_size)
{
    const int*   bits  = (const int*)  d_in[0];
    const float* pcm   = (const float*)d_in[1];
    const float* alpha = (const float*)d_in[2];
    float*       out   = (float*)d_out;

    const int grid = (NFRAMES + WPB - 1) / WPB;   // 7680 blocks
    burg_residual_kernel<<<grid, THREADS>>>(bits, pcm, alpha, out);
}

// round 5
// speedup vs baseline: 2.2793x; 1.2933x over previous
#include <cuda_runtime.h>

// ResidualEmbedding: per-frame Burg LPC (order 12) residual, sign-modulated embed.
// R5: TWO frames per warp, 16 lanes per frame, 10 contiguous samples per lane.
//  - Warp reductions: 4-step xor butterfly (8/4/2/1) stays inside each 16-lane
//    half -> one instruction stream reduces both frames simultaneously.
//  - Burg in j-space with zero-propagation invariant (no masks in dot/den).
//  - Shared frame rows padded to 161 floats: frame-B lanes hit odd banks,
//    frame-A even banks -> conflict-free window loads.
//  - FIR register-resident in two 17-float window passes (5 outputs each).

namespace {

constexpr int FRAME   = 160;
constexpr int KFR     = 15;
constexpr int ORDER   = 12;
constexpr int BATCH   = 4096;
constexpr int NFRAMES = BATCH * KFR;     // 61440
constexpr int WPB     = 8;               // warps per block (16 frames/block)
constexpr int THREADS = WPB * 32;
constexpr int ROWP    = 161;             // padded frame row (floats)
constexpr unsigned FULL = 0xffffffffu;

// reduce over each 16-lane half independently (both frames at once)
__device__ __forceinline__ float half_sum(float v) {
#pragma unroll
    for (int o = 8; o > 0; o >>= 1) v += __shfl_xor_sync(FULL, v, o);
    return v;
}

__global__ __launch_bounds__(THREADS) void burg_residual_kernel(
    const int*   __restrict__ bits,
    const float* __restrict__ pcm,
    const float* __restrict__ alpha_p,
    float*       __restrict__ out)
{
    const int warp   = threadIdx.x >> 5;
    const int lane   = threadIdx.x & 31;
    const int frame0 = (blockIdx.x * WPB + warp) * 2;   // grid exact: no bounds check

    __shared__ float shX[WPB][2 * ROWP];
    float* __restrict__ Xw = shX[warp];

    // ---- Coalesced load of both frames (320 contiguous floats) ----
    const float* __restrict__ src = pcm + (long long)frame0 * FRAME;
#pragma unroll
    for (int q = 0; q < 10; ++q) {
        const int m = lane + 32 * q;
        Xw[m + (m >= FRAME ? 1 : 0)] = src[m];
    }
    __syncwarp();

    const int half = lane >> 4;        // which frame in the pair
    const int lh   = lane & 15;        // lane within frame
    const int jb   = lh * 10;          // my contiguous j-range start
    float* __restrict__ Xf = Xw + half * ROWP;

    // ---- Window (np.hanning: 0.5 - 0.5*cos(2*pi*j/159)) ----
    float xw[10];
#pragma unroll
    for (int c = 0; c < 10; ++c) {
        const int j = jb + c;
        const float w = 0.5f - 0.5f * __cosf((6.283185307179586f / 159.0f) * (float)j);
        xw[c] = Xf[j] * w;
    }

    // ---- Init: b[j]=xw[j], f[j]=xw[j+1] (valid j<=158); j=159 kept at 0 ----
    float f[10], b[10];
#pragma unroll
    for (int c = 0; c < 10; ++c) b[c] = xw[c];
#pragma unroll
    for (int c = 0; c < 9; ++c) f[c] = xw[c + 1];
    {
        const float nxt = __shfl_sync(FULL, xw[0], lane + 1);
        f[9] = (lh == 15) ? 0.f : nxt;
    }
    if (lh == 15) b[9] = 0.f;

    float p0 = 0.f;
#pragma unroll
    for (int c = 0; c < 10; ++c) p0 += f[c] * f[c] + b[c] * b[c];
    float den = half_sum(p0);

    float a[ORDER + 1];
    a[0] = 1.f;
#pragma unroll
    for (int k = 1; k <= ORDER; ++k) a[k] = 0.f;

    // ---- Burg recursion. Invariant at iter i entry: f[j]=b[j]=0 for j>=159-i ----
#pragma unroll
    for (int i = 0; i < ORDER; ++i) {
        float p = 0.f;
#pragma unroll
        for (int c = 0; c < 10; ++c) p += f[c] * b[c];
        const float s = half_sum(p);
        const float r = -2.f * s / den;

        float t[10], u[10];
#pragma unroll
        for (int c = 0; c < 10; ++c) {
            t[c] = fmaf(r, b[c], f[c]);   // new f (pre-trim)
            u[c] = fmaf(r, f[c], b[c]);   // new b (pre-trim)
        }

        // den_{i+1} = (1-r^2)*den - u[158-i]^2 - t[0]^2   (per-half broadcasts)
        const int jl = 158 - i;           // compile-time under unroll
        const int Ll = jl / 10, cl = jl % 10;
        const float t0 = __shfl_sync(FULL, t[0],  half << 4);
        const float ul = __shfl_sync(FULL, u[cl], (half << 4) | Ll);
        den = (1.f - r * r) * den - ul * ul - t0 * t0;

        // f' = shift-by-1(t); b' = u with newly-invalid element zeroed
        const float tn = __shfl_sync(FULL, t[0], lane + 1);
#pragma unroll
        for (int c = 0; c < 9; ++c) f[c] = t[c + 1];
        f[9] = (lh == 15) ? 0.f : tn;
#pragma unroll
        for (int c = 0; c < 10; ++c) b[c] = u[c];
        if (lh == Ll) b[cl] = 0.f;

        // a[:i+2] += r * reverse(a[:i+2])  -- pairwise in place
#pragma unroll
        for (int k = 0; 2 * k <= i + 1; ++k) {
            const int k2 = i + 1 - k;
            if (k2 == k) {
                a[k] = a[k] + r * a[k];
            } else {
                const float tmp = a[k];
                a[k]  = fmaf(r, a[k2], a[k]);
                a[k2] = fmaf(r, tmp,  a[k2]);
            }
        }
    }

    // ---- FIR on raw samples (two 17-float window passes) + embed ----
    const int fr = frame0 + half;
    const float sgn  = 2.f * (float)__ldg(&bits[fr]) - 1.f;
    const float coef = __ldg(alpha_p) * sgn;

    float o[10];
    {   // outputs c=0..4, window X[jb-12 .. jb+4]
        float xf[17];
#pragma unroll
        for (int t = 0; t < 17; ++t) {
            const int idx = jb - 12 + t;
            xf[t] = (idx >= 0) ? Xf[idx] : 0.f;
        }
#pragma unroll
        for (int c = 0; c < 5; ++c) {
            float acc = a[0] * xf[12 + c];
#pragma unroll
            for (int k = 1; k <= ORDER; ++k)
                acc = fmaf(a[k], xf[12 + c - k], acc);
            o[c] = fmaf(coef, acc, xf[12 + c]);
        }
    }
    {   // outputs c=5..9, window X[jb-7 .. jb+9]
        float xf[17];
#pragma unroll
        for (int t = 0; t < 17; ++t) {
            const int idx = jb - 7 + t;
            xf[t] = (idx >= 0) ? Xf[idx] : 0.f;
        }
#pragma unroll
        for (int c2 = 0; c2 < 5; ++c2) {
            float acc = a[0] * xf[12 + c2];
#pragma unroll
            for (int k = 1; k <= ORDER; ++k)
                acc = fmaf(a[k], xf[12 + c2 - k], acc);
            o[5 + c2] = fmaf(coef, acc, xf[12 + c2]);
        }
    }

    // ---- Store back via shared for coalesced STG ----
    __syncwarp();
#pragma unroll
    for (int c = 0; c < 10; ++c) Xf[jb + c] = o[c];
    __syncwarp();

    float* __restrict__ dst = out + (long long)frame0 * FRAME;
#pragma unroll
    for (int q = 0; q < 10; ++q) {
        const int m = lane + 32 * q;
        dst[m] = Xw[m + (m >= FRAME ? 1 : 0)];
    }
}

} // namespace

extern "C" void kernel_launch(void* const* d_in, const int* in_sizes, int n_in,
                              void* d_out, int out_size)
{
    const int*   bits  = (const int*)  d_in[0];
    const float* pcm   = (const float*)d_in[1];
    const float* alpha = (const float*)d_in[2];
    float*       out   = (float*)d_out;

    const int grid = NFRAMES / (WPB * 2);   // 3840 blocks
    burg_residual_kernel<<<grid, THREADS>>>(bits, pcm, alpha, out);
}